// round 1
// baseline (speedup 1.0000x reference)
#include <cuda_runtime.h>
#include <cstdint>

// Problem constants
static constexpr int B = 32;
static constexpr int L = 4096;
static constexpr int C = 8;
static constexpr int T = 64;
static constexpr long long NELEM = (long long)B * L * C;   // 1,048,576

static constexpr int RED_BLOCKS  = 1024;
static constexpr int RED_THREADS = 256;
static constexpr int RED_PER_THR = 4;   // 1024*256*4 == NELEM exactly

// Deterministic scratch (no atomics -> bitwise reproducible per call)
__device__ double g_psum[RED_BLOCKS];
__device__ double g_psumsq[RED_BLOCKS];
__device__ float  g_mean;
__device__ float  g_inv;   // rsqrt.approx(var + eps)

__device__ __forceinline__ float rsqrt_approx(float x) {
    float r;
    asm("rsqrt.approx.f32 %0, %1;" : "=f"(r) : "f"(x));
    return r;
}

// ---------------------------------------------------------------------------
// K1: per-block partial sums of delta and delta^2 (double accumulation).
// delta[b,l,c] = in[b,l,c] - in[b,l-1,c], 0 at l==0. Layout: ((b*L)+l)*C + c.
// ---------------------------------------------------------------------------
__global__ void reduce_kernel(const float* __restrict__ in) {
    const int tid    = blockIdx.x * blockDim.x + threadIdx.x;
    const int stride = RED_BLOCKS * RED_THREADS;   // 262144

    double s = 0.0, ss = 0.0;
    #pragma unroll
    for (int k = 0; k < RED_PER_THR; ++k) {
        int idx = tid + k * stride;
        int bl  = idx >> 3;                 // /C
        int l   = bl & (L - 1);
        float delta = 0.0f;
        if (l != 0) delta = in[idx] - in[idx - C];
        double dd = (double)delta;
        s  += dd;
        ss += dd * dd;
    }

    __shared__ double sh_s[RED_THREADS];
    __shared__ double sh_q[RED_THREADS];
    int t = threadIdx.x;
    sh_s[t] = s;
    sh_q[t] = ss;
    __syncthreads();
    for (int o = RED_THREADS / 2; o > 0; o >>= 1) {
        if (t < o) { sh_s[t] += sh_s[t + o]; sh_q[t] += sh_q[t + o]; }
        __syncthreads();
    }
    if (t == 0) {
        g_psum[blockIdx.x]   = sh_s[0];
        g_psumsq[blockIdx.x] = sh_q[0];
    }
}

// ---------------------------------------------------------------------------
// K2: single-block finalize -> mean (f32) and rsqrt.approx(var_f32 + 1e-5f)
// ---------------------------------------------------------------------------
__global__ void finalize_kernel() {
    __shared__ double sh_s[RED_BLOCKS];
    __shared__ double sh_q[RED_BLOCKS];
    int t = threadIdx.x;           // 1024 threads
    sh_s[t] = g_psum[t];
    sh_q[t] = g_psumsq[t];
    __syncthreads();
    for (int o = RED_BLOCKS / 2; o > 0; o >>= 1) {
        if (t < o) { sh_s[t] += sh_s[t + o]; sh_q[t] += sh_q[t + o]; }
        __syncthreads();
    }
    if (t == 0) {
        double mean = sh_s[0] / (double)NELEM;
        double var  = sh_q[0] / (double)NELEM - mean * mean;
        float  vf   = (float)var + 1e-5f;
        g_mean = (float)mean;
        g_inv  = rsqrt_approx(vf);
    }
}

// ---------------------------------------------------------------------------
// K3: main — normalize delta, encode across T=64, LIF recurrence, spike out.
// One thread = 4 consecutive l for one (b, c). float4 store per timestep.
// out layout: [B, T, C, L] -> ((b*T + t)*C + c)*L + l
// ---------------------------------------------------------------------------
__global__ void __launch_bounds__(256) lif_kernel(
    const float* __restrict__ in,
    const float* __restrict__ enc_w,
    const float* __restrict__ enc_b,
    const float* __restrict__ bn_gamma,
    const float* __restrict__ bn_beta,
    float* __restrict__ out)
{
    __shared__ float sw[T];
    __shared__ float sb[T];
    if (threadIdx.x < T) {
        sw[threadIdx.x] = enc_w[threadIdx.x];   // enc_w is [T,1]
        sb[threadIdx.x] = enc_b[threadIdx.x];
    }
    __syncthreads();

    const int idx = blockIdx.x * blockDim.x + threadIdx.x;  // 0 .. 262143
    const int lv  = idx & ((L / 4) - 1);        // 0..1023
    const int c   = (idx >> 10) & (C - 1);
    const int b   = idx >> 13;
    const int l0  = lv * 4;

    const float mean = g_mean;
    const float inv  = g_inv;
    const float ga   = bn_gamma[0];
    const float be   = bn_beta[0];

    const float* inp = in + ((long long)b * L) * C + c;

    float d[4];
    #pragma unroll
    for (int j = 0; j < 4; ++j) {
        int l = l0 + j;
        float delta = (l == 0) ? 0.0f : (inp[l * C] - inp[(l - 1) * C]);
        // reference order: ((delta - mean) * rsqrt) * gamma + beta
        float x = (delta - mean) * inv;
        x = x * ga;
        d[j] = x + be;
    }

    float v0 = 0.0f, v1 = 0.0f, v2 = 0.0f, v3 = 0.0f;
    float* op = out + (((long long)b * T) * C + c) * L + l0;

    #pragma unroll 8
    for (int t = 0; t < T; ++t) {
        const float w  = sw[t];
        const float bb = sb[t];
        float4 s4;

        float x0 = fmaf(d[0], w, bb);
        v0 = v0 + (x0 - v0) * 0.5f;
        bool sp0 = (v0 >= 1.0f);
        s4.x = sp0 ? 1.0f : 0.0f;
        v0 = sp0 ? 0.0f : v0;

        float x1 = fmaf(d[1], w, bb);
        v1 = v1 + (x1 - v1) * 0.5f;
        bool sp1 = (v1 >= 1.0f);
        s4.y = sp1 ? 1.0f : 0.0f;
        v1 = sp1 ? 0.0f : v1;

        float x2 = fmaf(d[2], w, bb);
        v2 = v2 + (x2 - v2) * 0.5f;
        bool sp2 = (v2 >= 1.0f);
        s4.z = sp2 ? 1.0f : 0.0f;
        v2 = sp2 ? 0.0f : v2;

        float x3 = fmaf(d[3], w, bb);
        v3 = v3 + (x3 - v3) * 0.5f;
        bool sp3 = (v3 >= 1.0f);
        s4.w = sp3 ? 1.0f : 0.0f;
        v3 = sp3 ? 0.0f : v3;

        *reinterpret_cast<float4*>(op + (long long)t * (C * L)) = s4;
    }
}

// ---------------------------------------------------------------------------
extern "C" void kernel_launch(void* const* d_in, const int* in_sizes, int n_in,
                              void* d_out, int out_size)
{
    const float* in       = (const float*)d_in[0];
    const float* bn_gamma = (const float*)d_in[1];
    const float* bn_beta  = (const float*)d_in[2];
    const float* enc_w    = (const float*)d_in[3];
    const float* enc_b    = (const float*)d_in[4];
    float* out            = (float*)d_out;

    reduce_kernel<<<RED_BLOCKS, RED_THREADS>>>(in);
    finalize_kernel<<<1, RED_BLOCKS>>>();

    const int total_thr = B * C * (L / 4);      // 262144
    lif_kernel<<<total_thr / 256, 256>>>(in, enc_w, enc_b, bn_gamma, bn_beta, out);
}

// round 2
// speedup vs baseline: 1.2367x; 1.2367x over previous
#include <cuda_runtime.h>
#include <cstdint>

// Problem constants
static constexpr int B = 32;
static constexpr int L = 4096;
static constexpr int C = 8;
static constexpr int T = 64;
static constexpr long long NELEM = (long long)B * L * C;   // 1,048,576

static constexpr int RED_BLOCKS  = 256;
static constexpr int RED_THREADS = 256;
static constexpr int RED_PER_THR = 16;   // 256*256*16 == NELEM exactly

// Deterministic scratch (no atomics -> bitwise reproducible per call)
__device__ double g_psum[RED_BLOCKS];
__device__ double g_psumsq[RED_BLOCKS];
__device__ float  g_mean;
__device__ float  g_inv;   // rsqrt.approx(var + eps)

__device__ __forceinline__ float rsqrt_approx(float x) {
    float r;
    asm("rsqrt.approx.f32 %0, %1;" : "=f"(r) : "f"(x));
    return r;
}

// ---------------------------------------------------------------------------
// K1: per-block partial sums of delta and delta^2.
// f32 accumulation in the hot loop (16 elems/thread: error ~16*eps on a
// partial, irrelevant downstream since mean/inv are consumed in f32), double
// only in the 8-level shared tree. Removes the fp64-pipe bottleneck.
// delta[b,l,c] = in[b,l,c] - in[b,l-1,c], 0 at l==0. Layout: ((b*L)+l)*C + c.
// ---------------------------------------------------------------------------
__global__ void __launch_bounds__(RED_THREADS) reduce_kernel(const float* __restrict__ in) {
    const int tid    = blockIdx.x * blockDim.x + threadIdx.x;
    const int stride = RED_BLOCKS * RED_THREADS;   // 65536

    float s = 0.0f, ss = 0.0f;
    #pragma unroll
    for (int k = 0; k < RED_PER_THR; ++k) {
        int idx = tid + k * stride;
        int bl  = idx >> 3;                 // /C
        int l   = bl & (L - 1);
        float delta = 0.0f;
        if (l != 0) delta = in[idx] - in[idx - C];
        s  += delta;
        ss = fmaf(delta, delta, ss);
    }

    __shared__ double sh_s[RED_THREADS];
    __shared__ double sh_q[RED_THREADS];
    int t = threadIdx.x;
    sh_s[t] = (double)s;
    sh_q[t] = (double)ss;
    __syncthreads();
    for (int o = RED_THREADS / 2; o > 0; o >>= 1) {
        if (t < o) { sh_s[t] += sh_s[t + o]; sh_q[t] += sh_q[t + o]; }
        __syncthreads();
    }
    if (t == 0) {
        g_psum[blockIdx.x]   = sh_s[0];
        g_psumsq[blockIdx.x] = sh_q[0];
    }
}

// ---------------------------------------------------------------------------
// K2: single-block finalize -> mean (f32) and rsqrt.approx(var_f32 + 1e-5f)
// ---------------------------------------------------------------------------
__global__ void finalize_kernel() {
    __shared__ double sh_s[RED_BLOCKS];
    __shared__ double sh_q[RED_BLOCKS];
    int t = threadIdx.x;           // 256 threads
    sh_s[t] = g_psum[t];
    sh_q[t] = g_psumsq[t];
    __syncthreads();
    for (int o = RED_BLOCKS / 2; o > 0; o >>= 1) {
        if (t < o) { sh_s[t] += sh_s[t + o]; sh_q[t] += sh_q[t + o]; }
        __syncthreads();
    }
    if (t == 0) {
        double mean = sh_s[0] / (double)NELEM;
        double var  = sh_q[0] / (double)NELEM - mean * mean;
        float  vf   = (float)var + 1e-5f;
        g_mean = (float)mean;
        g_inv  = rsqrt_approx(vf);
    }
}

// ---------------------------------------------------------------------------
// K3: main — normalize delta, encode across T=64, LIF recurrence, spike out.
// One thread = 8 l's for one (b, c), as two disjoint 4-chunks at lA and
// lA + L/2 so every float4 store instruction is a full warp-contiguous 512B
// burst (line-complete, no interleaving). Streaming stores (.cs): output is
// never re-read.
// out layout: [B, T, C, L] -> ((b*T + t)*C + c)*L + l
// ---------------------------------------------------------------------------
__global__ void __launch_bounds__(256) lif_kernel(
    const float* __restrict__ in,
    const float* __restrict__ enc_w,
    const float* __restrict__ enc_b,
    const float* __restrict__ bn_gamma,
    const float* __restrict__ bn_beta,
    float* __restrict__ out)
{
    __shared__ float sw[T];
    __shared__ float sb[T];
    if (threadIdx.x < T) {
        sw[threadIdx.x] = enc_w[threadIdx.x];   // enc_w is [T,1]
        sb[threadIdx.x] = enc_b[threadIdx.x];
    }
    __syncthreads();

    const int idx = blockIdx.x * blockDim.x + threadIdx.x;  // 0 .. 131071
    const int lv  = idx & ((L / 8) - 1);        // 0..511
    const int c   = (idx >> 9) & (C - 1);
    const int b   = idx >> 12;
    const int lA  = lv * 4;                     // chunk A: [lA, lA+4)
    const int lB  = lA + (L / 2);               // chunk B: [lB, lB+4)

    const float mean = g_mean;
    const float inv  = g_inv;
    const float ga   = bn_gamma[0];
    const float be   = bn_beta[0];

    const float* inp = in + ((long long)b * L) * C + c;

    float dA[4], dB[4];
    #pragma unroll
    for (int j = 0; j < 4; ++j) {
        int la = lA + j;
        float deltaA = (la == 0) ? 0.0f : (inp[la * C] - inp[(la - 1) * C]);
        float xa = (deltaA - mean) * inv;
        dA[j] = xa * ga + be;

        int lb = lB + j;
        float deltaB = inp[lb * C] - inp[(lb - 1) * C];   // lB >= 2048, never 0
        float xb = (deltaB - mean) * inv;
        dB[j] = xb * ga + be;
    }

    float vA0 = 0.f, vA1 = 0.f, vA2 = 0.f, vA3 = 0.f;
    float vB0 = 0.f, vB1 = 0.f, vB2 = 0.f, vB3 = 0.f;

    float* opA = out + (((long long)b * T) * C + c) * L + lA;
    float* opB = opA + (L / 2);

    #pragma unroll 8
    for (int t = 0; t < T; ++t) {
        const float w  = sw[t];
        const float bb = sb[t];
        const long long off = (long long)t * (C * L);
        float4 sa, sbv;

        float x;
        x = fmaf(dA[0], w, bb); vA0 = vA0 + (x - vA0) * 0.5f;
        bool p0 = (vA0 >= 1.0f); sa.x = p0 ? 1.0f : 0.0f; vA0 = p0 ? 0.0f : vA0;
        x = fmaf(dA[1], w, bb); vA1 = vA1 + (x - vA1) * 0.5f;
        bool p1 = (vA1 >= 1.0f); sa.y = p1 ? 1.0f : 0.0f; vA1 = p1 ? 0.0f : vA1;
        x = fmaf(dA[2], w, bb); vA2 = vA2 + (x - vA2) * 0.5f;
        bool p2 = (vA2 >= 1.0f); sa.z = p2 ? 1.0f : 0.0f; vA2 = p2 ? 0.0f : vA2;
        x = fmaf(dA[3], w, bb); vA3 = vA3 + (x - vA3) * 0.5f;
        bool p3 = (vA3 >= 1.0f); sa.w = p3 ? 1.0f : 0.0f; vA3 = p3 ? 0.0f : vA3;

        x = fmaf(dB[0], w, bb); vB0 = vB0 + (x - vB0) * 0.5f;
        bool q0 = (vB0 >= 1.0f); sbv.x = q0 ? 1.0f : 0.0f; vB0 = q0 ? 0.0f : vB0;
        x = fmaf(dB[1], w, bb); vB1 = vB1 + (x - vB1) * 0.5f;
        bool q1 = (vB1 >= 1.0f); sbv.y = q1 ? 1.0f : 0.0f; vB1 = q1 ? 0.0f : vB1;
        x = fmaf(dB[2], w, bb); vB2 = vB2 + (x - vB2) * 0.5f;
        bool q2 = (vB2 >= 1.0f); sbv.z = q2 ? 1.0f : 0.0f; vB2 = q2 ? 0.0f : vB2;
        x = fmaf(dB[3], w, bb); vB3 = vB3 + (x - vB3) * 0.5f;
        bool q3 = (vB3 >= 1.0f); sbv.w = q3 ? 1.0f : 0.0f; vB3 = q3 ? 0.0f : vB3;

        __stcs(reinterpret_cast<float4*>(opA + off), sa);
        __stcs(reinterpret_cast<float4*>(opB + off), sbv);
    }
}

// ---------------------------------------------------------------------------
extern "C" void kernel_launch(void* const* d_in, const int* in_sizes, int n_in,
                              void* d_out, int out_size)
{
    const float* in       = (const float*)d_in[0];
    const float* bn_gamma = (const float*)d_in[1];
    const float* bn_beta  = (const float*)d_in[2];
    const float* enc_w    = (const float*)d_in[3];
    const float* enc_b    = (const float*)d_in[4];
    float* out            = (float*)d_out;

    reduce_kernel<<<RED_BLOCKS, RED_THREADS>>>(in);
    finalize_kernel<<<1, RED_BLOCKS>>>();

    const int total_thr = B * C * (L / 8);      // 131072
    lif_kernel<<<total_thr / 256, 256>>>(in, enc_w, enc_b, bn_gamma, bn_beta, out);
}